// round 7
// baseline (speedup 1.0000x reference)
#include <cuda_runtime.h>

#define NT 256
#define PADL 4

// SMEM arena (float offsets), lifetimes:
#define OFF_A1E  0      // 2064 = 4+2050+8(+2)  live B..C
#define OFF_A1O  2064   // 2064                 live B..C
#define OFF_A2E  4128   // 1040 = 4+1027+8(+1)  live C..D
#define OFF_A2O  5168   // 1040                 live C..D
#define OFF_D2   6208   // 2060 (2054+2 slack)  live C..D
#define OFF_A3   0      // 1032 (over dead a1)  live D..E
#define OFF_D3   1040   // 1032 (over dead a1)  live D..E
#define OFF_S1   4128   // 2060 (over dead a2)  live E..F
#define OFF_S0   6188   // 2060 (over dead d2)  live E..F
#define ARENA    8268   // 33072 B -> 6 CTAs/SM

// Filters
#define DL0 -0.0105974018f
#define DL1  0.0328830117f
#define DL2  0.0308413818f
#define DL3 -0.1870348117f
#define DL4 -0.0279837694f
#define DL5  0.6308807679f
#define DL6  0.7148465706f
#define DL7  0.2303778133f

__device__ __forceinline__ float gload(const float* __restrict__ x, int t) {
    t = (t < 0) ? -t : t;
    t = (t >= 8192) ? (16382 - t) : t;
    return x[t];
}

// Level-1 LO-only analysis straight from gmem -> a1 split (+pads). M=4100, G=1025.
__device__ __forceinline__ void analysis_l1_lo(const float* __restrict__ xr,
                                               float* __restrict__ ae, float* __restrict__ ao)
{
    const float WL[8] = {DL0, DL1, DL2, DL3, DL4, DL5, DL6, DL7};
    const int M = 4100, G = 1025, LeN = 2050;
    for (int g = threadIdx.x; g < G; g += NT) {
        float v[16];
        if (g >= 1 && g <= G - 2) {
            const float4* p = reinterpret_cast<const float4*>(xr + 8 * g - 8);
            float4 q0 = p[0], q1 = p[1], q2 = p[2], q3 = p[3];
            v[0]=q0.x; v[1]=q0.y; v[2]=q0.z; v[3]=q0.w;
            v[4]=q1.x; v[5]=q1.y; v[6]=q1.z; v[7]=q1.w;
            v[8]=q2.x; v[9]=q2.y; v[10]=q2.z; v[11]=q2.w;
            v[12]=q3.x; v[13]=q3.y; v[14]=q3.z; v[15]=q3.w;
        } else {
            #pragma unroll
            for (int j = 0; j < 16; j++) v[j] = gload(xr, 8 * g - 8 + j);
        }
        float lo[4];
        #pragma unroll
        for (int r = 0; r < 4; r++) {
            float a = WL[0] * v[2*r+1];
            #pragma unroll
            for (int k = 1; k < 8; k++) a = fmaf(WL[k], v[2*r+1+k], a);
            lo[r] = a;
        }
        *reinterpret_cast<float2*>(ae + 2 * g) = make_float2(lo[0], lo[2]);
        *reinterpret_cast<float2*>(ao + 2 * g) = make_float2(lo[1], lo[3]);
        if (g < 3 || g > G - 6) {   // mirrored pads for next level
            #pragma unroll
            for (int r = 0; r < 4; r++) {
                const int m = 4 * g + r;
                if (m >= 1 && m <= 8) {
                    if (m & 1) ao[-((m + 1) >> 1)] = lo[r];
                    else       ae[-(m >> 1)]       = lo[r];
                }
                if (m >= M - 17 && m <= M - 2) {
                    if (m & 1) ao[LeN + ((M - 3 - m) >> 1)] = lo[r];
                    else       ae[LeN + ((M - 2 - m) >> 1)] = lo[r];
                }
            }
        }
    }
}

// band3 fused: HI-synth(HI-analysis(x)) gmem->gmem, no smem. 1024 groups x 8 outputs.
__device__ __forceinline__ void band3_fused(const float* __restrict__ xr, float* __restrict__ out)
{
    const float WH[8] = {-0.2303778133f, 0.7148465706f, -0.6308807679f, -0.0279837694f,
                          0.1870348117f, 0.0308413818f, -0.0328830117f, -0.0105974018f};
    // REC_HI synth weights
    const float r0 = -0.0105974018f, r1 = -0.0328830117f, r2 =  0.0308413818f, r3 =  0.1870348117f;
    const float r4 = -0.0279837694f, r5 = -0.6308807679f, r6 =  0.7148465706f, r7 = -0.2303778133f;
    const int G = 1024;
    for (int g = threadIdx.x; g < G; g += NT) {
        float v[24];
        if (g >= 1 && g <= G - 2) {
            const float4* p = reinterpret_cast<const float4*>(xr + 8 * g - 8);
            #pragma unroll
            for (int j = 0; j < 6; j++) {
                float4 q = p[j];
                v[4*j] = q.x; v[4*j+1] = q.y; v[4*j+2] = q.z; v[4*j+3] = q.w;
            }
        } else {
            #pragma unroll
            for (int j = 0; j < 24; j++) v[j] = gload(xr, 8 * g - 8 + j);
        }
        float D[8];   // d1[4g .. 4g+7]
        #pragma unroll
        for (int r = 0; r < 8; r++) {
            float a = WH[0] * v[2*r+1];
            #pragma unroll
            for (int k = 1; k < 8; k++) a = fmaf(WH[k], v[2*r+1+k], a);
            D[r] = a;
        }
        float4 o0, o1;
        o0.x = fmaf(r7, D[0], fmaf(r5, D[1], fmaf(r3, D[2], r1 * D[3])));
        o0.y = fmaf(r6, D[1], fmaf(r4, D[2], fmaf(r2, D[3], r0 * D[4])));
        o0.z = fmaf(r7, D[1], fmaf(r5, D[2], fmaf(r3, D[3], r1 * D[4])));
        o0.w = fmaf(r6, D[2], fmaf(r4, D[3], fmaf(r2, D[4], r0 * D[5])));
        o1.x = fmaf(r7, D[2], fmaf(r5, D[3], fmaf(r3, D[4], r1 * D[5])));
        o1.y = fmaf(r6, D[3], fmaf(r4, D[4], fmaf(r2, D[5], r0 * D[6])));
        o1.z = fmaf(r7, D[3], fmaf(r5, D[4], fmaf(r3, D[5], r1 * D[6])));
        o1.w = fmaf(r6, D[4], fmaf(r4, D[5], fmaf(r2, D[6], r0 * D[7])));
        float4* po = reinterpret_cast<float4*>(out + 8 * g);
        po[0] = o0; po[1] = o1;
    }
}

// Split-input analysis for levels 2/3 (smem even/odd halves with pads).
template<bool SPLIT>
__device__ __forceinline__ void analysis_v(
    const float* __restrict__ xe, const float* __restrict__ xo, int M,
    float* __restrict__ ae, float* __restrict__ ao, int LeN,
    float* __restrict__ loc, float* __restrict__ hic)
{
    const float A0=-0.0105974018f, A1= 0.0308413818f, A2=-0.0279837694f, A3= 0.7148465706f;
    const float B0= 0.0328830117f, B1=-0.1870348117f, B2= 0.6308807679f, B3= 0.2303778133f;
    const float C0=-0.2303778133f, C1=-0.6308807679f, C2= 0.1870348117f, C3=-0.0328830117f;
    const float E0= 0.7148465706f, E1=-0.0279837694f, E2= 0.0308413818f, E3=-0.0105974018f;
    const int G = (M + 3) >> 2;
    for (int g = threadIdx.x; g < G; g += NT) {
        const int m0 = 4 * g;
        float4 oa = *reinterpret_cast<const float4*>(xo + 4*g - 4);
        float4 ob = *reinterpret_cast<const float4*>(xo + 4*g);
        float4 ea = *reinterpret_cast<const float4*>(xe + 4*g - 4);
        float4 eb = *reinterpret_cast<const float4*>(xe + 4*g);
        float ov[8] = {oa.x,oa.y,oa.z,oa.w,ob.x,ob.y,ob.z,ob.w};
        float ev[8] = {ea.x,ea.y,ea.z,ea.w,eb.x,eb.y,eb.z,eb.w};
        float lo[4], hi[4];
        #pragma unroll
        for (int r = 0; r < 4; r++) {
            lo[r] = fmaf(A0, ov[r], fmaf(A1, ov[r+1], fmaf(A2, ov[r+2], fmaf(A3, ov[r+3],
                    fmaf(B0, ev[r+1], fmaf(B1, ev[r+2], fmaf(B2, ev[r+3], B3*ev[r+4])))))));
            hi[r] = fmaf(C0, ov[r], fmaf(C1, ov[r+1], fmaf(C2, ov[r+2], fmaf(C3, ov[r+3],
                    fmaf(E0, ev[r+1], fmaf(E1, ev[r+2], fmaf(E2, ev[r+3], E3*ev[r+4])))))));
        }
        if (m0 + 3 < M) {
            *reinterpret_cast<float4*>(hic + m0) = make_float4(hi[0],hi[1],hi[2],hi[3]);
            if (SPLIT) {
                *reinterpret_cast<float2*>(ae + 2*g) = make_float2(lo[0], lo[2]);
                *reinterpret_cast<float2*>(ao + 2*g) = make_float2(lo[1], lo[3]);
            } else {
                *reinterpret_cast<float4*>(loc + m0) = make_float4(lo[0],lo[1],lo[2],lo[3]);
            }
        } else {
            #pragma unroll
            for (int r = 0; r < 4; r++) if (m0 + r < M) {
                hic[m0+r] = hi[r];
                if (SPLIT) { int m = m0 + r; if (m & 1) ao[m>>1] = lo[r]; else ae[m>>1] = lo[r]; }
                else loc[m0+r] = lo[r];
            }
        }
        if (SPLIT && (g < 3 || m0 + 3 >= M - 17)) {
            #pragma unroll
            for (int r = 0; r < 4; r++) {
                const int m = m0 + r;
                if (m >= 1 && m <= 8) {
                    if (m & 1) ao[-((m+1)>>1)] = lo[r];
                    else       ae[-(m>>1)]     = lo[r];
                }
                if (m >= M-17 && m <= M-2) {
                    if (m & 1) ao[LeN + ((M-3-m)>>1)] = lo[r];
                    else       ae[LeN + ((M-2-m)>>1)] = lo[r];
                }
            }
        }
    }
}

// Plain transpose-conv stride2 + crop7 into smem: in[Lin] -> out[2*Lin-8].
template<bool HIF>
__device__ __forceinline__ void synth_v(const float* __restrict__ in, int Lin, float* __restrict__ out)
{
    const float w0 = HIF ? -0.0105974018f :  0.2303778133f;
    const float w1 = HIF ? -0.0328830117f :  0.7148465706f;
    const float w2 = HIF ?  0.0308413818f :  0.6308807679f;
    const float w3 = HIF ?  0.1870348117f : -0.0279837694f;
    const float w4 = HIF ? -0.0279837694f : -0.1870348117f;
    const float w5 = HIF ? -0.6308807679f :  0.0308413818f;
    const float w6 = HIF ?  0.7148465706f :  0.0328830117f;
    const float w7 = HIF ? -0.2303778133f : -0.0105974018f;
    const int Q = Lin - 4;
    const int N4 = Q >> 2;
    for (int t = threadIdx.x; t < N4; t += NT) {
        float4 a = *reinterpret_cast<const float4*>(in + 4*t);
        float4 b = *reinterpret_cast<const float4*>(in + 4*t + 4);
        float v[8] = {a.x,a.y,a.z,a.w,b.x,b.y,b.z,b.w};
        float e[4], o[4];
        #pragma unroll
        for (int j = 0; j < 4; j++) {
            e[j] = fmaf(w7, v[j],   fmaf(w5, v[j+1], fmaf(w3, v[j+2], w1*v[j+3])));
            o[j] = fmaf(w6, v[j+1], fmaf(w4, v[j+2], fmaf(w2, v[j+3], w0*v[j+4])));
        }
        *reinterpret_cast<float4*>(out + 8*t)     = make_float4(e[0],o[0],e[1],o[1]);
        *reinterpret_cast<float4*>(out + 8*t + 4) = make_float4(e[2],o[2],e[3],o[3]);
    }
    const int rem = Q & 3;
    if (threadIdx.x < rem) {
        const int q = (N4 << 2) + threadIdx.x;
        float x0=in[q], x1=in[q+1], x2=in[q+2], x3=in[q+3], x4=in[q+4];
        out[2*q]   = fmaf(w7,x0,fmaf(w5,x1,fmaf(w3,x2,w1*x3)));
        out[2*q+1] = fmaf(w6,x1,fmaf(w4,x2,fmaf(w2,x3,w0*x4)));
    }
}

// Fused double-synth: outer LO( inner (in) ), in[2054] smem -> out[8192] gmem.
// 512 groups x 16 outputs. Reads in[4t..4t+11] (over-read slack 2; used: 4t..4t+9).
template<bool INNER_HIF>
__device__ __forceinline__ void fused2(const float* __restrict__ in, float* __restrict__ out)
{
    const float i0 = INNER_HIF ? -0.0105974018f :  0.2303778133f;
    const float i1 = INNER_HIF ? -0.0328830117f :  0.7148465706f;
    const float i2 = INNER_HIF ?  0.0308413818f :  0.6308807679f;
    const float i3 = INNER_HIF ?  0.1870348117f : -0.0279837694f;
    const float i4 = INNER_HIF ? -0.0279837694f : -0.1870348117f;
    const float i5 = INNER_HIF ? -0.6308807679f :  0.0308413818f;
    const float i6 = INNER_HIF ?  0.7148465706f :  0.0328830117f;
    const float i7 = INNER_HIF ? -0.2303778133f : -0.0105974018f;
    const float L0 =  0.2303778133f, L1 =  0.7148465706f, L2 =  0.6308807679f, L3 = -0.0279837694f;
    const float L4 = -0.1870348117f, L5 =  0.0308413818f, L6 =  0.0328830117f, L7 = -0.0105974018f;
    for (int t = threadIdx.x; t < 512; t += NT) {
        float v[12];
        const float4* p = reinterpret_cast<const float4*>(in + 4 * t);
        #pragma unroll
        for (int j = 0; j < 3; j++) {
            float4 q = p[j];
            v[4*j] = q.x; v[4*j+1] = q.y; v[4*j+2] = q.z; v[4*j+3] = q.w;
        }
        float T[12];   // inner[8t .. 8t+11]
        #pragma unroll
        for (int l = 0; l < 6; l++) {
            T[2*l]   = fmaf(i7, v[l],   fmaf(i5, v[l+1], fmaf(i3, v[l+2], i1*v[l+3])));
            T[2*l+1] = fmaf(i6, v[l+1], fmaf(i4, v[l+2], fmaf(i2, v[l+3], i0*v[l+4])));
        }
        float4* po = reinterpret_cast<float4*>(out + 16 * t);
        #pragma unroll
        for (int h = 0; h < 4; h++) {
            float4 o;
            o.x = fmaf(L7, T[2*h],   fmaf(L5, T[2*h+1], fmaf(L3, T[2*h+2], L1*T[2*h+3])));
            o.y = fmaf(L6, T[2*h+1], fmaf(L4, T[2*h+2], fmaf(L2, T[2*h+3], L0*T[2*h+4])));
            o.z = fmaf(L7, T[2*h+1], fmaf(L5, T[2*h+2], fmaf(L3, T[2*h+3], L1*T[2*h+4])));
            o.w = fmaf(L6, T[2*h+2], fmaf(L4, T[2*h+3], fmaf(L2, T[2*h+4], L0*T[2*h+5])));
            po[h] = o;
        }
    }
}

__global__ void __launch_bounds__(NT, 6)
dwt_kernel(const float* __restrict__ x, float* __restrict__ out)
{
    extern __shared__ float s[];
    const int row = blockIdx.x;                  // 0..2047
    const float* __restrict__ xr = x + (size_t)row * 8192;

    float* a1e = s + OFF_A1E + PADL;  float* a1o = s + OFF_A1O + PADL;
    float* a2e = s + OFF_A2E + PADL;  float* a2o = s + OFF_A2O + PADL;
    float* d2 = s + OFF_D2;  float* d3 = s + OFF_D3;
    float* a3 = s + OFF_A3;  float* s1 = s + OFF_S1;  float* s0 = s + OFF_S0;

    // B: level-1 LO analysis from gmem: x -> a1(split,+pads)
    analysis_l1_lo(xr, a1e, a1o);
    __syncthreads();

    // C: band3 fused (gmem x -> gmem) || level-2 analysis: a1 -> a2(split,+pads), d2
    band3_fused(xr, out + ((size_t)(3*2048 + row)) * 8192);
    analysis_v<true>(a1e, a1o, 2054, a2e, a2o, 1027, nullptr, d2);
    __syncthreads();

    // D: band2 = LO∘HI fused (d2 -> gmem) || level-3 analysis: a2 -> a3, d3
    fused2<true>(d2, out + ((size_t)(2*2048 + row)) * 8192);
    analysis_v<false>(a2e, a2o, 1031, nullptr, nullptr, 0, a3, d3);
    __syncthreads();

    // E: s1 = HI-synth(d3) (2054) || s0 = LO-synth(a3) (2054)
    synth_v<true>(d3, 1031, s1);
    synth_v<false>(a3, 1031, s0);
    __syncthreads();

    // F: band1 = LO∘LO fused (s1 -> gmem) || band0 = LO∘LO fused (s0 -> gmem)
    fused2<false>(s1, out + ((size_t)(1*2048 + row)) * 8192);
    fused2<false>(s0, out + (size_t)row * 8192);
}

extern "C" void kernel_launch(void* const* d_in, const int* in_sizes, int n_in,
                              void* d_out, int out_size)
{
    const float* x = (const float*)d_in[0];
    float* out = (float*)d_out;
    cudaFuncSetAttribute(dwt_kernel, cudaFuncAttributeMaxDynamicSharedMemorySize,
                         ARENA * (int)sizeof(float));
    dwt_kernel<<<2048, NT, ARENA * sizeof(float)>>>(x, out);
}

// round 8
// speedup vs baseline: 1.4862x; 1.4862x over previous
#include <cuda_runtime.h>

#define NT 256
#define PADL 4

// SMEM arena (float offsets), lifetimes:
#define OFF_A1E  0      // 2064                 live B..C
#define OFF_A1O  2064   // 2064                 live B..C
#define OFF_D1   4128   // 4104                 live B..C
#define OFF_A2E  8232   // 1040                 live C..D
#define OFF_A2O  9272   // 1040                 live C..D
#define OFF_D2   10312  // 2056 -> 12368        live C..D
#define OFF_A3   0      // 1032 (over dead a1)  live D..E
#define OFF_D3   1032   // 1032 (over dead a1)  live D..E
#define OFF_S1   4128   // 2056 (over dead d1)  live E..F
#define OFF_S0   6188   // 2056 (dead d1/a2e)   live E..F
#define ARENA    12368  // 49472 B -> 4 CTAs/SM

__device__ __forceinline__ float gload(const float* __restrict__ x, int t) {
    t = (t < 0) ? -t : t;
    t = (t >= 8192) ? (16382 - t) : t;
    return x[t];
}

// Level-1 analysis from gmem: x -> a1 split(+pads) + d1 contig. M=4100, G=1025.
__device__ __forceinline__ void analysis_l1(const float* __restrict__ xr,
                                            float* __restrict__ ae, float* __restrict__ ao,
                                            float* __restrict__ hic)
{
    const float WL[8] = {-0.0105974018f, 0.0328830117f, 0.0308413818f, -0.1870348117f,
                         -0.0279837694f, 0.6308807679f, 0.7148465706f,  0.2303778133f};
    const float WH[8] = {-0.2303778133f, 0.7148465706f, -0.6308807679f, -0.0279837694f,
                          0.1870348117f, 0.0308413818f, -0.0328830117f, -0.0105974018f};
    const int M = 4100, G = 1025, LeN = 2050;
    for (int g = threadIdx.x; g < G; g += NT) {
        float v[16];
        if (g >= 1 && g <= G - 2) {
            const float4* p = reinterpret_cast<const float4*>(xr + 8 * g - 8);
            float4 q0 = p[0], q1 = p[1], q2 = p[2], q3 = p[3];
            v[0]=q0.x; v[1]=q0.y; v[2]=q0.z; v[3]=q0.w;
            v[4]=q1.x; v[5]=q1.y; v[6]=q1.z; v[7]=q1.w;
            v[8]=q2.x; v[9]=q2.y; v[10]=q2.z; v[11]=q2.w;
            v[12]=q3.x; v[13]=q3.y; v[14]=q3.z; v[15]=q3.w;
        } else {
            #pragma unroll
            for (int j = 0; j < 16; j++) v[j] = gload(xr, 8 * g - 8 + j);
        }
        float lo[4], hi[4];
        #pragma unroll
        for (int r = 0; r < 4; r++) {
            float accl = WL[0] * v[2*r+1], acch = WH[0] * v[2*r+1];
            #pragma unroll
            for (int k = 1; k < 8; k++) {
                accl = fmaf(WL[k], v[2*r+1+k], accl);
                acch = fmaf(WH[k], v[2*r+1+k], acch);
            }
            lo[r] = accl; hi[r] = acch;
        }
        *reinterpret_cast<float4*>(hic + 4 * g) = make_float4(hi[0], hi[1], hi[2], hi[3]);
        *reinterpret_cast<float2*>(ae + 2 * g) = make_float2(lo[0], lo[2]);
        *reinterpret_cast<float2*>(ao + 2 * g) = make_float2(lo[1], lo[3]);
        if (g < 3 || g > G - 6) {   // mirrored pads for next level
            #pragma unroll
            for (int r = 0; r < 4; r++) {
                const int m = 4 * g + r;
                if (m >= 1 && m <= 8) {
                    if (m & 1) ao[-((m + 1) >> 1)] = lo[r];
                    else       ae[-(m >> 1)]       = lo[r];
                }
                if (m >= M - 17 && m <= M - 2) {
                    if (m & 1) ao[LeN + ((M - 3 - m) >> 1)] = lo[r];
                    else       ae[LeN + ((M - 2 - m) >> 1)] = lo[r];
                }
            }
        }
    }
}

// Split-input analysis for levels 2/3.
template<bool SPLIT>
__device__ __forceinline__ void analysis_v(
    const float* __restrict__ xe, const float* __restrict__ xo, int M,
    float* __restrict__ ae, float* __restrict__ ao, int LeN,
    float* __restrict__ loc, float* __restrict__ hic)
{
    const float A0=-0.0105974018f, A1= 0.0308413818f, A2=-0.0279837694f, A3= 0.7148465706f;
    const float B0= 0.0328830117f, B1=-0.1870348117f, B2= 0.6308807679f, B3= 0.2303778133f;
    const float C0=-0.2303778133f, C1=-0.6308807679f, C2= 0.1870348117f, C3=-0.0328830117f;
    const float E0= 0.7148465706f, E1=-0.0279837694f, E2= 0.0308413818f, E3=-0.0105974018f;
    const int G = (M + 3) >> 2;
    for (int g = threadIdx.x; g < G; g += NT) {
        const int m0 = 4 * g;
        float4 oa = *reinterpret_cast<const float4*>(xo + 4*g - 4);
        float4 ob = *reinterpret_cast<const float4*>(xo + 4*g);
        float4 ea = *reinterpret_cast<const float4*>(xe + 4*g - 4);
        float4 eb = *reinterpret_cast<const float4*>(xe + 4*g);
        float ov[8] = {oa.x,oa.y,oa.z,oa.w,ob.x,ob.y,ob.z,ob.w};
        float ev[8] = {ea.x,ea.y,ea.z,ea.w,eb.x,eb.y,eb.z,eb.w};
        float lo[4], hi[4];
        #pragma unroll
        for (int r = 0; r < 4; r++) {
            lo[r] = fmaf(A0, ov[r], fmaf(A1, ov[r+1], fmaf(A2, ov[r+2], fmaf(A3, ov[r+3],
                    fmaf(B0, ev[r+1], fmaf(B1, ev[r+2], fmaf(B2, ev[r+3], B3*ev[r+4])))))));
            hi[r] = fmaf(C0, ov[r], fmaf(C1, ov[r+1], fmaf(C2, ov[r+2], fmaf(C3, ov[r+3],
                    fmaf(E0, ev[r+1], fmaf(E1, ev[r+2], fmaf(E2, ev[r+3], E3*ev[r+4])))))));
        }
        if (m0 + 3 < M) {
            *reinterpret_cast<float4*>(hic + m0) = make_float4(hi[0],hi[1],hi[2],hi[3]);
            if (SPLIT) {
                *reinterpret_cast<float2*>(ae + 2*g) = make_float2(lo[0], lo[2]);
                *reinterpret_cast<float2*>(ao + 2*g) = make_float2(lo[1], lo[3]);
            } else {
                *reinterpret_cast<float4*>(loc + m0) = make_float4(lo[0],lo[1],lo[2],lo[3]);
            }
        } else {
            #pragma unroll
            for (int r = 0; r < 4; r++) if (m0 + r < M) {
                hic[m0+r] = hi[r];
                if (SPLIT) { int m = m0 + r; if (m & 1) ao[m>>1] = lo[r]; else ae[m>>1] = lo[r]; }
                else loc[m0+r] = lo[r];
            }
        }
        if (SPLIT && (g < 3 || m0 + 3 >= M - 17)) {
            #pragma unroll
            for (int r = 0; r < 4; r++) {
                const int m = m0 + r;
                if (m >= 1 && m <= 8) {
                    if (m & 1) ao[-((m+1)>>1)] = lo[r];
                    else       ae[-(m>>1)]     = lo[r];
                }
                if (m >= M-17 && m <= M-2) {
                    if (m & 1) ao[LeN + ((M-3-m)>>1)] = lo[r];
                    else       ae[LeN + ((M-2-m)>>1)] = lo[r];
                }
            }
        }
    }
}

// Transpose-conv stride2 + crop7, thread-contiguous float4 outputs (1x coalesced).
// out[4k..4k+3] from in[2k..2k+5]. Lout = 2*Lin-8.
template<bool HIF>
__device__ __forceinline__ void synth4(const float* __restrict__ in, int Lin, float* __restrict__ out)
{
    const float w0 = HIF ? -0.0105974018f :  0.2303778133f;
    const float w1 = HIF ? -0.0328830117f :  0.7148465706f;
    const float w2 = HIF ?  0.0308413818f :  0.6308807679f;
    const float w3 = HIF ?  0.1870348117f : -0.0279837694f;
    const float w4 = HIF ? -0.0279837694f : -0.1870348117f;
    const float w5 = HIF ? -0.6308807679f :  0.0308413818f;
    const float w6 = HIF ?  0.7148465706f :  0.0328830117f;
    const float w7 = HIF ? -0.2303778133f : -0.0105974018f;
    const int Lout = 2 * Lin - 8;
    const int NG = Lout >> 2;
    float4* o4 = reinterpret_cast<float4*>(out);
    for (int k = threadIdx.x; k < NG; k += NT) {
        float2 a = *reinterpret_cast<const float2*>(in + 2*k);
        float2 b = *reinterpret_cast<const float2*>(in + 2*k + 2);
        float2 c = *reinterpret_cast<const float2*>(in + 2*k + 4);
        float v0=a.x, v1=a.y, v2=b.x, v3=b.y, v4=c.x, v5=c.y;
        float4 o;
        o.x = fmaf(w7, v0, fmaf(w5, v1, fmaf(w3, v2, w1 * v3)));
        o.y = fmaf(w6, v1, fmaf(w4, v2, fmaf(w2, v3, w0 * v4)));
        o.z = fmaf(w7, v1, fmaf(w5, v2, fmaf(w3, v3, w1 * v4)));
        o.w = fmaf(w6, v2, fmaf(w4, v3, fmaf(w2, v4, w0 * v5)));
        o4[k] = o;
    }
    const int rem = Lout & 3;   // 0 or 2 in our shapes
    if (rem && threadIdx.x < rem) {
        const int p = (NG << 2) + threadIdx.x;
        const int q = p >> 1;
        float r;
        if ((p & 1) == 0)
            r = fmaf(w7, in[q],   fmaf(w5, in[q+1], fmaf(w3, in[q+2], w1 * in[q+3])));
        else
            r = fmaf(w6, in[q+1], fmaf(w4, in[q+2], fmaf(w2, in[q+3], w0 * in[q+4])));
        out[p] = r;
    }
}

// Fused double synth: outer LO ∘ inner<INNER_HIF>, in[2054] smem -> out[8192] gmem.
// Thread-contiguous float4 outputs: out[4k..4k+3] from in[k..k+6].
template<bool INNER_HIF>
__device__ __forceinline__ void fused2g(const float* __restrict__ in, float* __restrict__ out)
{
    const float i0 = INNER_HIF ? -0.0105974018f :  0.2303778133f;
    const float i1 = INNER_HIF ? -0.0328830117f :  0.7148465706f;
    const float i2 = INNER_HIF ?  0.0308413818f :  0.6308807679f;
    const float i3 = INNER_HIF ?  0.1870348117f : -0.0279837694f;
    const float i4 = INNER_HIF ? -0.0279837694f : -0.1870348117f;
    const float i5 = INNER_HIF ? -0.6308807679f :  0.0308413818f;
    const float i6 = INNER_HIF ?  0.7148465706f :  0.0328830117f;
    const float i7 = INNER_HIF ? -0.2303778133f : -0.0105974018f;
    const float L0 =  0.2303778133f, L1 =  0.7148465706f, L2 =  0.6308807679f, L3 = -0.0279837694f;
    const float L4 = -0.1870348117f, L5 =  0.0308413818f, L6 =  0.0328830117f, L7 = -0.0105974018f;
    float4* o4 = reinterpret_cast<float4*>(out);
    for (int k = threadIdx.x; k < 2048; k += NT) {
        float v[7];
        #pragma unroll
        for (int j = 0; j < 7; j++) v[j] = in[k + j];
        float T[6];
        #pragma unroll
        for (int l = 0; l < 3; l++) {
            T[2*l]   = fmaf(i7, v[l],   fmaf(i5, v[l+1], fmaf(i3, v[l+2], i1 * v[l+3])));
            T[2*l+1] = fmaf(i6, v[l+1], fmaf(i4, v[l+2], fmaf(i2, v[l+3], i0 * v[l+4])));
        }
        float4 o;
        o.x = fmaf(L7, T[0], fmaf(L5, T[1], fmaf(L3, T[2], L1 * T[3])));
        o.y = fmaf(L6, T[1], fmaf(L4, T[2], fmaf(L2, T[3], L0 * T[4])));
        o.z = fmaf(L7, T[1], fmaf(L5, T[2], fmaf(L3, T[3], L1 * T[4])));
        o.w = fmaf(L6, T[2], fmaf(L4, T[3], fmaf(L2, T[4], L0 * T[5])));
        o4[k] = o;
    }
}

__global__ void __launch_bounds__(NT, 4)
dwt_kernel(const float* __restrict__ x, float* __restrict__ out)
{
    extern __shared__ float s[];
    const int row = blockIdx.x;                  // 0..2047
    const float* __restrict__ xr = x + (size_t)row * 8192;

    float* a1e = s + OFF_A1E + PADL;  float* a1o = s + OFF_A1O + PADL;
    float* a2e = s + OFF_A2E + PADL;  float* a2o = s + OFF_A2O + PADL;
    float* d1 = s + OFF_D1;  float* d2 = s + OFF_D2;  float* d3 = s + OFF_D3;
    float* a3 = s + OFF_A3;  float* s1 = s + OFF_S1;  float* s0 = s + OFF_S0;

    // B: level-1 analysis from gmem: x -> a1(split,+pads), d1
    analysis_l1(xr, a1e, a1o, d1);
    __syncthreads();

    // C: band3 = HI-synth(d1) -> gmem (coalesced) || level-2: a1 -> a2(split,+pads), d2
    synth4<true>(d1, 4100, out + ((size_t)(3*2048 + row)) * 8192);
    analysis_v<true>(a1e, a1o, 2054, a2e, a2o, 1027, nullptr, d2);
    __syncthreads();

    // D: band2 = LO∘HI fused (d2 -> gmem) || level-3: a2 -> a3, d3
    fused2g<true>(d2, out + ((size_t)(2*2048 + row)) * 8192);
    analysis_v<false>(a2e, a2o, 1031, nullptr, nullptr, 0, a3, d3);
    __syncthreads();

    // E: s1 = HI-synth(d3) (2054) || s0 = LO-synth(a3) (2054)
    synth4<true>(d3, 1031, s1);
    synth4<false>(a3, 1031, s0);
    __syncthreads();

    // F: band1 = LO∘LO fused (s1 -> gmem) || band0 = LO∘LO fused (s0 -> gmem)
    fused2g<false>(s1, out + ((size_t)(1*2048 + row)) * 8192);
    fused2g<false>(s0, out + (size_t)row * 8192);
}

extern "C" void kernel_launch(void* const* d_in, const int* in_sizes, int n_in,
                              void* d_out, int out_size)
{
    const float* x = (const float*)d_in[0];
    float* out = (float*)d_out;
    cudaFuncSetAttribute(dwt_kernel, cudaFuncAttributeMaxDynamicSharedMemorySize,
                         ARENA * (int)sizeof(float));
    dwt_kernel<<<2048, NT, ARENA * sizeof(float)>>>(x, out);
}